// round 12
// baseline (speedup 1.0000x reference)
#include <cuda_runtime.h>
#include <cstdint>

#define BB 1024      // batch
#define DD 512       // feature dim
#define MM 256       // modes
#define THRESHV 1.0f
#define RB 8         // batch rows per scores-block
#define NCHUNK 4     // mode chunks for the fused kernel
#define MCH (MM / NCHUNK)   // 64 modes per chunk
#define LB 8         // load batch (MLP group) in fused kernel

// partial mixed accumulators, one slab per mode-chunk (deterministic reduce)
__device__ float g_partial[NCHUNK][BB * DD];   // 8 MB static scratch

// ---------------------------------------------------------------------------
// Kernel 1: scores[b,m] = softmax_m( dot(x[b,:], W[m,:]) + bias[m] )
// 128 blocks x 1024 threads. thread t: mode m = t&255, row-group g = t>>8
// owning rows 2g, 2g+1. 4x shorter FMA chains + 50% occupancy vs R7's 12.5%.
// ---------------------------------------------------------------------------
__global__ __launch_bounds__(1024)
void poly_scores_kernel(const float* __restrict__ x,
                        const float* __restrict__ W,
                        const float* __restrict__ bias,
                        float* __restrict__ scores)
{
    __shared__ float4 xs[RB * (DD / 4)];       // 16 KB
    __shared__ float  logits[RB][MM];          // 8 KB

    const int b0 = blockIdx.x * RB;
    const int t  = threadIdx.x;                // 0..1023
    const int m  = t & 255;                    // mode
    const int g  = t >> 8;                     // row group 0..3 -> rows 2g,2g+1

    // cooperatively load 8 x-rows (vectorized)
    const float4* x4 = reinterpret_cast<const float4*>(x + (size_t)b0 * DD);
    #pragma unroll
    for (int i = t; i < RB * (DD / 4); i += 1024) xs[i] = x4[i];
    __syncthreads();

    float a0 = 0.0f, a1 = 0.0f;
    const float4* w4  = reinterpret_cast<const float4*>(W + (size_t)m * DD);
    const float4* xr0 = &xs[(2 * g)     * (DD / 4)];
    const float4* xr1 = &xs[(2 * g + 1) * (DD / 4)];

    #pragma unroll 4
    for (int k = 0; k < DD / 4; ++k) {
        const float4 wv  = w4[k];
        const float4 xv0 = xr0[k];
        const float4 xv1 = xr1[k];
        a0 = fmaf(wv.x, xv0.x, a0); a0 = fmaf(wv.y, xv0.y, a0);
        a0 = fmaf(wv.z, xv0.z, a0); a0 = fmaf(wv.w, xv0.w, a0);
        a1 = fmaf(wv.x, xv1.x, a1); a1 = fmaf(wv.y, xv1.y, a1);
        a1 = fmaf(wv.z, xv1.z, a1); a1 = fmaf(wv.w, xv1.w, a1);
    }
    const float bv = bias[m];
    logits[2 * g][m]     = a0 + bv;
    logits[2 * g + 1][m] = a1 + bv;
    __syncthreads();

    // softmax: warps 0..7 handle rows 0..7 (256 elems, 8 per lane)
    if (t < 256) {
        const int w    = t >> 5;
        const int lane = t & 31;
        float v[8];
        float mx = -1e30f;
        #pragma unroll
        for (int j = 0; j < 8; ++j) { v[j] = logits[w][lane + 32 * j]; mx = fmaxf(mx, v[j]); }
        #pragma unroll
        for (int o = 16; o > 0; o >>= 1) mx = fmaxf(mx, __shfl_xor_sync(0xFFFFFFFFu, mx, o));
        float s = 0.0f;
        #pragma unroll
        for (int j = 0; j < 8; ++j) { v[j] = __expf(v[j] - mx); s += v[j]; }
        #pragma unroll
        for (int o = 16; o > 0; o >>= 1) s += __shfl_xor_sync(0xFFFFFFFFu, s, o);
        const float inv = 1.0f / s;

        float* srow = scores + (size_t)(b0 + w) * MM;
        #pragma unroll
        for (int j = 0; j < 8; ++j) srow[lane + 32 * j] = v[j] * inv;
    }
}

// ---------------------------------------------------------------------------
// Kernel 2: grid (1024 b, 4 mode-chunks) x 128 threads.
// Explicit 8-wide load batching: all 8 streaming loads issue before any
// compute, guaranteeing MLP_p1=8 per warp. launch_bounds(128,8) -> 64 regs
// for the batch at 8 blocks/SM (50% occ).
// ---------------------------------------------------------------------------
__global__ __launch_bounds__(128, 8)
void poly_fused_chunk_kernel(const float* __restrict__ x,
                             const float* __restrict__ mem,
                             const float* __restrict__ scores,
                             float* __restrict__ mem_new)
{
    __shared__ float s_sc[MCH];

    const int b  = blockIdx.x;
    const int c  = blockIdx.y;
    const int m0 = c * MCH;
    const int t  = threadIdx.x;                // 0..127 (float4 lane over D)

    if (t < MCH) s_sc[t] = scores[(size_t)b * MM + m0 + t];
    __syncthreads();

    const size_t base = (size_t)b * (DD / 4) + t;   // in float4 units
    const float4 xv   = reinterpret_cast<const float4*>(x)[base];

    const float4* m4 = reinterpret_cast<const float4*>(mem);
    float4*       o4 = reinterpret_cast<float4*>(mem_new);

    float4 acc = make_float4(0.f, 0.f, 0.f, 0.f);
    const size_t stride = (size_t)(BB * DD / 4);    // float4 per mode

    #pragma unroll
    for (int mo = 0; mo < MCH; mo += LB) {
        float4 mv[LB];
        #pragma unroll
        for (int j = 0; j < LB; ++j)
            mv[j] = __ldcs(m4 + base + (size_t)(m0 + mo + j) * stride);

        #pragma unroll
        for (int j = 0; j < LB; ++j) {
            const int   m    = m0 + mo + j;
            const float beta = (float)m / 257.0f;

            float4 mn;
            mn.x = fmaf(beta, mv[j].x, xv.x) - (mv[j].x > THRESHV ? 1.0f : 0.0f);
            mn.y = fmaf(beta, mv[j].y, xv.y) - (mv[j].y > THRESHV ? 1.0f : 0.0f);
            mn.z = fmaf(beta, mv[j].z, xv.z) - (mv[j].z > THRESHV ? 1.0f : 0.0f);
            mn.w = fmaf(beta, mv[j].w, xv.w) - (mv[j].w > THRESHV ? 1.0f : 0.0f);

            __stcs(o4 + base + (size_t)m * stride, mn);

            const float sc = s_sc[mo + j];
            acc.x += (mn.x - THRESHV > 0.0f) ? sc : 0.0f;
            acc.y += (mn.y - THRESHV > 0.0f) ? sc : 0.0f;
            acc.z += (mn.z - THRESHV > 0.0f) ? sc : 0.0f;
            acc.w += (mn.w - THRESHV > 0.0f) ? sc : 0.0f;
        }
    }

    reinterpret_cast<float4*>(&g_partial[c][0])[base] = acc;
}

// ---------------------------------------------------------------------------
// Kernel 3: mixed = sum over the 4 chunk partials. 18 MB traffic, ~3us.
// ---------------------------------------------------------------------------
__global__ __launch_bounds__(256)
void poly_reduce_kernel(float* __restrict__ mixed)
{
    const size_t i = (size_t)blockIdx.x * 256 + threadIdx.x;  // float4 index
    const float4 p0 = reinterpret_cast<const float4*>(&g_partial[0][0])[i];
    const float4 p1 = reinterpret_cast<const float4*>(&g_partial[1][0])[i];
    const float4 p2 = reinterpret_cast<const float4*>(&g_partial[2][0])[i];
    const float4 p3 = reinterpret_cast<const float4*>(&g_partial[3][0])[i];
    float4 r;
    r.x = (p0.x + p1.x) + (p2.x + p3.x);
    r.y = (p0.y + p1.y) + (p2.y + p3.y);
    r.z = (p0.z + p1.z) + (p2.z + p3.z);
    r.w = (p0.w + p1.w) + (p2.w + p3.w);
    reinterpret_cast<float4*>(mixed)[i] = r;
}

// ---------------------------------------------------------------------------
// Launch: outputs packed as [mixed (B*D) | mem_new (M*B*D) | scores (B*M)]
// ---------------------------------------------------------------------------
extern "C" void kernel_launch(void* const* d_in, const int* in_sizes, int n_in,
                              void* d_out, int out_size)
{
    const float* x    = (const float*)d_in[0];   // [B, D]
    const float* mem  = (const float*)d_in[1];   // [M, B, D]
    const float* W    = (const float*)d_in[2];   // [M, D]
    const float* bias = (const float*)d_in[3];   // [M]

    float* out     = (float*)d_out;
    float* mixed   = out;                                          // B*D
    float* mem_new = out + (size_t)BB * DD;                        // M*B*D
    float* scores  = out + (size_t)BB * DD + (size_t)MM * BB * DD; // B*M

    poly_scores_kernel<<<BB / RB, 1024>>>(x, W, bias, scores);
    poly_fused_chunk_kernel<<<dim3(BB, NCHUNK), 128>>>(x, mem, scores, mem_new);
    poly_reduce_kernel<<<(BB * DD / 4) / 256, 256>>>(mixed);
}

// round 13
// speedup vs baseline: 1.2201x; 1.2201x over previous
#include <cuda_runtime.h>
#include <cstdint>

#define BB 1024      // batch
#define DD 512       // feature dim
#define MM 256       // modes
#define THRESHV 1.0f
#define RB 8         // batch rows per scores-block
#define NCHUNK 4     // mode chunks for the fused kernel
#define MCH (MM / NCHUNK)   // 64 modes per chunk
#define LB 8         // load batch (MLP group) in fused kernel
#define KT 16        // k-tile (floats) for scores W staging
#define WPAD 20      // padded smem row stride (floats): 16 data + 4 pad

// partial mixed accumulators, one slab per mode-chunk (deterministic reduce)
__device__ float g_partial[NCHUNK][BB * DD];   // 8 MB static scratch

// ---------------------------------------------------------------------------
// Kernel 1: scores[b,m] = softmax_m( dot(x[b,:], W[m,:]) + bias[m] )
// 128 blocks x 256 threads, RB=8 rows/block, 8 accumulators/thread (ILP=8).
// W is staged through smem in KT=16 k-tiles with COALESCED global loads
// (vs. the old per-thread-row LDG pattern that touched 32 lines per warp).
// smem: xs 16KB + Wt 20KB + logits 8KB = 44KB (< 48KB static limit).
// ---------------------------------------------------------------------------
__global__ __launch_bounds__(256)
void poly_scores_kernel(const float* __restrict__ x,
                        const float* __restrict__ W,
                        const float* __restrict__ bias,
                        float* __restrict__ scores)
{
    __shared__ float4 xs[RB * (DD / 4)];       // 16 KB
    __shared__ float  Wt[MM * WPAD];           // 20 KB
    __shared__ float  logits[RB][MM];          // 8 KB

    const int b0 = blockIdx.x * RB;
    const int t  = threadIdx.x;                // 0..255 == mode index

    // cooperatively load 8 x-rows (vectorized, coalesced)
    const float4* x4 = reinterpret_cast<const float4*>(x + (size_t)b0 * DD);
    #pragma unroll
    for (int i = t; i < RB * (DD / 4); i += 256) xs[i] = x4[i];

    float acc[RB];
    #pragma unroll
    for (int r = 0; r < RB; ++r) acc[r] = 0.0f;

    const float4* Wg = reinterpret_cast<const float4*>(W);

    for (int k0 = 0; k0 < DD; k0 += KT) {
        __syncthreads();   // prev compute done before overwriting Wt (also guards xs 1st iter)
        // coop load W[:, k0:k0+KT]: 256 rows x 4 float4 = 1024 float4, coalesced.
        // i=t..: m = i/4, j = i%4 -> warp covers 8 rows x 4 float4 = whole 64B runs.
        #pragma unroll
        for (int i = t; i < MM * (KT / 4); i += 256) {
            const int m = i >> 2;
            const int j = i & 3;
            const float4 v = Wg[(size_t)m * (DD / 4) + (k0 >> 2) + j];
            *reinterpret_cast<float4*>(&Wt[m * WPAD + j * 4]) = v;
        }
        __syncthreads();
        // compute: thread t's W row from smem (<=2-way conflict), x broadcast
        #pragma unroll
        for (int kk = 0; kk < KT / 4; ++kk) {
            const float4 wv = *reinterpret_cast<const float4*>(&Wt[t * WPAD + kk * 4]);
            #pragma unroll
            for (int r = 0; r < RB; ++r) {
                const float4 xv = xs[r * (DD / 4) + (k0 >> 2) + kk];
                acc[r] = fmaf(wv.x, xv.x, acc[r]);
                acc[r] = fmaf(wv.y, xv.y, acc[r]);
                acc[r] = fmaf(wv.z, xv.z, acc[r]);
                acc[r] = fmaf(wv.w, xv.w, acc[r]);
            }
        }
    }

    const float bv = bias[t];
    #pragma unroll
    for (int r = 0; r < RB; ++r) logits[r][t] = acc[r] + bv;
    __syncthreads();

    // softmax: warp w handles row w (256 elems, 8 per lane)
    const int w    = t >> 5;
    const int lane = t & 31;
    float v[8];
    float mx = -1e30f;
    #pragma unroll
    for (int j = 0; j < 8; ++j) { v[j] = logits[w][lane + 32 * j]; mx = fmaxf(mx, v[j]); }
    #pragma unroll
    for (int o = 16; o > 0; o >>= 1) mx = fmaxf(mx, __shfl_xor_sync(0xFFFFFFFFu, mx, o));
    float s = 0.0f;
    #pragma unroll
    for (int j = 0; j < 8; ++j) { v[j] = __expf(v[j] - mx); s += v[j]; }
    #pragma unroll
    for (int o = 16; o > 0; o >>= 1) s += __shfl_xor_sync(0xFFFFFFFFu, s, o);
    const float inv = 1.0f / s;

    float* srow = scores + (size_t)(b0 + w) * MM;
    #pragma unroll
    for (int j = 0; j < 8; ++j) srow[lane + 32 * j] = v[j] * inv;
}

// ---------------------------------------------------------------------------
// Kernel 2 (UNCHANGED from R12 — measured ~163us): grid (1024 b, 4 chunks)
// x 128 threads, explicit 8-wide load batching for MLP_p1=8.
// ---------------------------------------------------------------------------
__global__ __launch_bounds__(128, 8)
void poly_fused_chunk_kernel(const float* __restrict__ x,
                             const float* __restrict__ mem,
                             const float* __restrict__ scores,
                             float* __restrict__ mem_new)
{
    __shared__ float s_sc[MCH];

    const int b  = blockIdx.x;
    const int c  = blockIdx.y;
    const int m0 = c * MCH;
    const int t  = threadIdx.x;                // 0..127 (float4 lane over D)

    if (t < MCH) s_sc[t] = scores[(size_t)b * MM + m0 + t];
    __syncthreads();

    const size_t base = (size_t)b * (DD / 4) + t;   // in float4 units
    const float4 xv   = reinterpret_cast<const float4*>(x)[base];

    const float4* m4 = reinterpret_cast<const float4*>(mem);
    float4*       o4 = reinterpret_cast<float4*>(mem_new);

    float4 acc = make_float4(0.f, 0.f, 0.f, 0.f);
    const size_t stride = (size_t)(BB * DD / 4);    // float4 per mode

    #pragma unroll
    for (int mo = 0; mo < MCH; mo += LB) {
        float4 mv[LB];
        #pragma unroll
        for (int j = 0; j < LB; ++j)
            mv[j] = __ldcs(m4 + base + (size_t)(m0 + mo + j) * stride);

        #pragma unroll
        for (int j = 0; j < LB; ++j) {
            const int   m    = m0 + mo + j;
            const float beta = (float)m / 257.0f;

            float4 mn;
            mn.x = fmaf(beta, mv[j].x, xv.x) - (mv[j].x > THRESHV ? 1.0f : 0.0f);
            mn.y = fmaf(beta, mv[j].y, xv.y) - (mv[j].y > THRESHV ? 1.0f : 0.0f);
            mn.z = fmaf(beta, mv[j].z, xv.z) - (mv[j].z > THRESHV ? 1.0f : 0.0f);
            mn.w = fmaf(beta, mv[j].w, xv.w) - (mv[j].w > THRESHV ? 1.0f : 0.0f);

            __stcs(o4 + base + (size_t)m * stride, mn);

            const float sc = s_sc[mo + j];
            acc.x += (mn.x - THRESHV > 0.0f) ? sc : 0.0f;
            acc.y += (mn.y - THRESHV > 0.0f) ? sc : 0.0f;
            acc.z += (mn.z - THRESHV > 0.0f) ? sc : 0.0f;
            acc.w += (mn.w - THRESHV > 0.0f) ? sc : 0.0f;
        }
    }

    reinterpret_cast<float4*>(&g_partial[c][0])[base] = acc;
}

// ---------------------------------------------------------------------------
// Kernel 3: mixed = sum over the 4 chunk partials. 18 MB traffic, ~3us.
// ---------------------------------------------------------------------------
__global__ __launch_bounds__(256)
void poly_reduce_kernel(float* __restrict__ mixed)
{
    const size_t i = (size_t)blockIdx.x * 256 + threadIdx.x;  // float4 index
    const float4 p0 = reinterpret_cast<const float4*>(&g_partial[0][0])[i];
    const float4 p1 = reinterpret_cast<const float4*>(&g_partial[1][0])[i];
    const float4 p2 = reinterpret_cast<const float4*>(&g_partial[2][0])[i];
    const float4 p3 = reinterpret_cast<const float4*>(&g_partial[3][0])[i];
    float4 r;
    r.x = (p0.x + p1.x) + (p2.x + p3.x);
    r.y = (p0.y + p1.y) + (p2.y + p3.y);
    r.z = (p0.z + p1.z) + (p2.z + p3.z);
    r.w = (p0.w + p1.w) + (p2.w + p3.w);
    reinterpret_cast<float4*>(mixed)[i] = r;
}

// ---------------------------------------------------------------------------
// Launch: outputs packed as [mixed (B*D) | mem_new (M*B*D) | scores (B*M)]
// ---------------------------------------------------------------------------
extern "C" void kernel_launch(void* const* d_in, const int* in_sizes, int n_in,
                              void* d_out, int out_size)
{
    const float* x    = (const float*)d_in[0];   // [B, D]
    const float* mem  = (const float*)d_in[1];   // [M, B, D]
    const float* W    = (const float*)d_in[2];   // [M, D]
    const float* bias = (const float*)d_in[3];   // [M]

    float* out     = (float*)d_out;
    float* mixed   = out;                                          // B*D
    float* mem_new = out + (size_t)BB * DD;                        // M*B*D
    float* scores  = out + (size_t)BB * DD + (size_t)MM * BB * DD; // B*M

    poly_scores_kernel<<<BB / RB, 256>>>(x, W, bias, scores);
    poly_fused_chunk_kernel<<<dim3(BB, NCHUNK), 128>>>(x, mem, scores, mem_new);
    poly_reduce_kernel<<<(BB * DD / 4) / 256, 256>>>(mixed);
}

// round 14
// speedup vs baseline: 1.2254x; 1.0044x over previous
#include <cuda_runtime.h>
#include <cstdint>

#define BB 1024      // batch
#define DD 512       // feature dim
#define MM 256       // modes
#define THRESHV 1.0f
#define RB 8         // batch rows per scores-block
#define NCHUNK 4     // mode chunks for the fused kernel
#define MCH (MM / NCHUNK)   // 64 modes per chunk
#define LB 8         // load batch (MLP group) in fused kernel
#define WTS 257      // padded Wt row stride (floats): 256 modes + 1

// partial mixed accumulators, one slab per mode-chunk (deterministic reduce)
__device__ float g_partial[NCHUNK][BB * DD];   // 8 MB static scratch

// ---------------------------------------------------------------------------
// Kernel 1: scores[b,m] = softmax_m( dot(x[b,:], W[m,:]) + bias[m] )
// 128 blocks x 1024 threads. thread t: mode m = t&255, row-group g = t>>8
// (owns batch rows 2g, 2g+1). W staged through smem in 16-float k-tiles,
// TRANSPOSED layout Wt[k][m] (padded stride 257) -> compute-side LDS is
// lane-consecutive = conflict-free. Next tile's W float4 is prefetched
// before compute to hide L2 latency. 32 warps/SM (50% occ) vs R13's 8.
// k-order per (row,mode) identical to R13 -> bit-identical logits.
// smem: xs 16KB + Wt 16.1KB + logits 8KB = ~40KB static.
// ---------------------------------------------------------------------------
__global__ __launch_bounds__(1024)
void poly_scores_kernel(const float* __restrict__ x,
                        const float* __restrict__ W,
                        const float* __restrict__ bias,
                        float* __restrict__ scores)
{
    __shared__ float4 xs[RB * (DD / 4)];       // 16 KB (1024 float4)
    __shared__ float  Wt[16 * WTS];            // 16 k-slots x 257 floats
    __shared__ float  logits[RB][MM];          // 8 KB

    const int b0 = blockIdx.x * RB;
    const int t  = threadIdx.x;                // 0..1023
    const int m  = t & 255;                    // mode
    const int g  = t >> 8;                     // row group -> rows 2g, 2g+1

    // load 8 x-rows: exactly one float4 per thread, coalesced
    xs[t] = reinterpret_cast<const float4*>(x + (size_t)b0 * DD)[t];

    // staging mapping: one float4 of W per thread per tile
    const int sm = t >> 2;                     // staging mode row
    const int sj = t & 3;                      // float4 index within tile
    const float4* Wg = reinterpret_cast<const float4*>(W);
    const size_t wbase = (size_t)sm * (DD / 4) + sj;

    float a0 = 0.0f, a1 = 0.0f;
    float4 v = Wg[wbase];                      // prefetch tile 0

    const float4* xr0 = &xs[(2 * g)     * (DD / 4)];
    const float4* xr1 = &xs[(2 * g + 1) * (DD / 4)];

    #pragma unroll 1
    for (int k0 = 0; k0 < DD / 4; k0 += 4) {   // 32 tiles of 4 float4 (16 floats)
        __syncthreads();                        // Wt free; (1st iter: xs ready)
        Wt[(sj * 4 + 0) * WTS + sm] = v.x;      // transposed store, <=2-way
        Wt[(sj * 4 + 1) * WTS + sm] = v.y;
        Wt[(sj * 4 + 2) * WTS + sm] = v.z;
        Wt[(sj * 4 + 3) * WTS + sm] = v.w;
        if (k0 + 4 < DD / 4) v = Wg[wbase + k0 + 4];   // prefetch next tile
        __syncthreads();

        #pragma unroll
        for (int kk = 0; kk < 4; ++kk) {
            const float w0 = Wt[(kk * 4 + 0) * WTS + m];   // conflict-free
            const float w1 = Wt[(kk * 4 + 1) * WTS + m];
            const float w2 = Wt[(kk * 4 + 2) * WTS + m];
            const float w3 = Wt[(kk * 4 + 3) * WTS + m];
            const float4 xv0 = xr0[k0 + kk];               // warp broadcast
            const float4 xv1 = xr1[k0 + kk];
            a0 = fmaf(w0, xv0.x, a0); a0 = fmaf(w1, xv0.y, a0);
            a0 = fmaf(w2, xv0.z, a0); a0 = fmaf(w3, xv0.w, a0);
            a1 = fmaf(w0, xv1.x, a1); a1 = fmaf(w1, xv1.y, a1);
            a1 = fmaf(w2, xv1.z, a1); a1 = fmaf(w3, xv1.w, a1);
        }
    }

    const float bv = bias[m];
    logits[2 * g][m]     = a0 + bv;            // each group owns its rows
    logits[2 * g + 1][m] = a1 + bv;
    __syncthreads();

    // softmax: warps 0..7 handle rows 0..7 (256 elems, 8 per lane)
    if (t < 256) {
        const int w    = t >> 5;
        const int lane = t & 31;
        float vv[8];
        float mx = -1e30f;
        #pragma unroll
        for (int j = 0; j < 8; ++j) { vv[j] = logits[w][lane + 32 * j]; mx = fmaxf(mx, vv[j]); }
        #pragma unroll
        for (int o = 16; o > 0; o >>= 1) mx = fmaxf(mx, __shfl_xor_sync(0xFFFFFFFFu, mx, o));
        float s = 0.0f;
        #pragma unroll
        for (int j = 0; j < 8; ++j) { vv[j] = __expf(vv[j] - mx); s += vv[j]; }
        #pragma unroll
        for (int o = 16; o > 0; o >>= 1) s += __shfl_xor_sync(0xFFFFFFFFu, s, o);
        const float inv = 1.0f / s;

        float* srow = scores + (size_t)(b0 + w) * MM;
        #pragma unroll
        for (int j = 0; j < 8; ++j) srow[lane + 32 * j] = vv[j] * inv;
    }
}

// ---------------------------------------------------------------------------
// Kernel 2 (UNCHANGED — measured ~161us, ~6.6TB/s): grid (1024 b, 4 chunks)
// x 128 threads, explicit 8-wide load batching for MLP_p1=8.
// ---------------------------------------------------------------------------
__global__ __launch_bounds__(128, 8)
void poly_fused_chunk_kernel(const float* __restrict__ x,
                             const float* __restrict__ mem,
                             const float* __restrict__ scores,
                             float* __restrict__ mem_new)
{
    __shared__ float s_sc[MCH];

    const int b  = blockIdx.x;
    const int c  = blockIdx.y;
    const int m0 = c * MCH;
    const int t  = threadIdx.x;                // 0..127 (float4 lane over D)

    if (t < MCH) s_sc[t] = scores[(size_t)b * MM + m0 + t];
    __syncthreads();

    const size_t base = (size_t)b * (DD / 4) + t;   // in float4 units
    const float4 xv   = reinterpret_cast<const float4*>(x)[base];

    const float4* m4 = reinterpret_cast<const float4*>(mem);
    float4*       o4 = reinterpret_cast<float4*>(mem_new);

    float4 acc = make_float4(0.f, 0.f, 0.f, 0.f);
    const size_t stride = (size_t)(BB * DD / 4);    // float4 per mode

    #pragma unroll
    for (int mo = 0; mo < MCH; mo += LB) {
        float4 mv[LB];
        #pragma unroll
        for (int j = 0; j < LB; ++j)
            mv[j] = __ldcs(m4 + base + (size_t)(m0 + mo + j) * stride);

        #pragma unroll
        for (int j = 0; j < LB; ++j) {
            const int   m    = m0 + mo + j;
            const float beta = (float)m / 257.0f;

            float4 mn;
            mn.x = fmaf(beta, mv[j].x, xv.x) - (mv[j].x > THRESHV ? 1.0f : 0.0f);
            mn.y = fmaf(beta, mv[j].y, xv.y) - (mv[j].y > THRESHV ? 1.0f : 0.0f);
            mn.z = fmaf(beta, mv[j].z, xv.z) - (mv[j].z > THRESHV ? 1.0f : 0.0f);
            mn.w = fmaf(beta, mv[j].w, xv.w) - (mv[j].w > THRESHV ? 1.0f : 0.0f);

            __stcs(o4 + base + (size_t)m * stride, mn);

            const float sc = s_sc[mo + j];
            acc.x += (mn.x - THRESHV > 0.0f) ? sc : 0.0f;
            acc.y += (mn.y - THRESHV > 0.0f) ? sc : 0.0f;
            acc.z += (mn.z - THRESHV > 0.0f) ? sc : 0.0f;
            acc.w += (mn.w - THRESHV > 0.0f) ? sc : 0.0f;
        }
    }

    reinterpret_cast<float4*>(&g_partial[c][0])[base] = acc;
}

// ---------------------------------------------------------------------------
// Kernel 3: mixed = sum over the 4 chunk partials. 18 MB traffic, ~3us.
// ---------------------------------------------------------------------------
__global__ __launch_bounds__(256)
void poly_reduce_kernel(float* __restrict__ mixed)
{
    const size_t i = (size_t)blockIdx.x * 256 + threadIdx.x;  // float4 index
    const float4 p0 = reinterpret_cast<const float4*>(&g_partial[0][0])[i];
    const float4 p1 = reinterpret_cast<const float4*>(&g_partial[1][0])[i];
    const float4 p2 = reinterpret_cast<const float4*>(&g_partial[2][0])[i];
    const float4 p3 = reinterpret_cast<const float4*>(&g_partial[3][0])[i];
    float4 r;
    r.x = (p0.x + p1.x) + (p2.x + p3.x);
    r.y = (p0.y + p1.y) + (p2.y + p3.y);
    r.z = (p0.z + p1.z) + (p2.z + p3.z);
    r.w = (p0.w + p1.w) + (p2.w + p3.w);
    reinterpret_cast<float4*>(mixed)[i] = r;
}

// ---------------------------------------------------------------------------
// Launch: outputs packed as [mixed (B*D) | mem_new (M*B*D) | scores (B*M)]
// ---------------------------------------------------------------------------
extern "C" void kernel_launch(void* const* d_in, const int* in_sizes, int n_in,
                              void* d_out, int out_size)
{
    const float* x    = (const float*)d_in[0];   // [B, D]
    const float* mem  = (const float*)d_in[1];   // [M, B, D]
    const float* W    = (const float*)d_in[2];   // [M, D]
    const float* bias = (const float*)d_in[3];   // [M]

    float* out     = (float*)d_out;
    float* mixed   = out;                                          // B*D
    float* mem_new = out + (size_t)BB * DD;                        // M*B*D
    float* scores  = out + (size_t)BB * DD + (size_t)MM * BB * DD; // B*M

    poly_scores_kernel<<<BB / RB, 1024>>>(x, W, bias, scores);
    poly_fused_chunk_kernel<<<dim3(BB, NCHUNK), 128>>>(x, mem, scores, mem_new);
    poly_reduce_kernel<<<(BB * DD / 4) / 256, 256>>>(mixed);
}